// round 10
// baseline (speedup 1.0000x reference)
#include <cuda_runtime.h>
#include <cuda_bf16.h>
#include <cstdint>

#define NN 50000
#define EE 800000
#define DD 128
#define OUTD 64
#define NG 64

// Scratch (device globals; no allocation allowed)
__device__ float g_agg[NN * DD];
__device__ float g_bufA[NN * DD];
__device__ float g_bufB[NN * DD];
__device__ float g_pool[NG * DD];
__device__ float g_cnt[NG];
__device__ int   g_deg[NN];
__device__ int   g_rowptr[NN + 1];
__device__ int   g_csr[EE];
// Pre-split weights: 6 matrices [W1l, W1r, W2l, W2r, W3l, W3r], each 128x128
__device__ uint16_t g_wH[6 * 128 * 128];
__device__ uint16_t g_wL[6 * 128 * 128];

// ===========================================================================
// PTX helpers
// ===========================================================================
__device__ __forceinline__ uint32_t smem_u32(const void* p) {
    uint32_t a;
    asm("{ .reg .u64 t; cvta.to.shared.u64 t, %1; cvt.u32.u64 %0, t; }" : "=r"(a) : "l"(p));
    return a;
}
#define CP_ASYNC16(dst, src) \
    asm volatile("cp.async.cg.shared.global [%0], [%1], 16;" :: "r"(dst), "l"(src) : "memory")
#define CP_COMMIT() asm volatile("cp.async.commit_group;" ::: "memory")
#define CP_WAIT0()  asm volatile("cp.async.wait_group 0;" ::: "memory")
#define LDM4(r, a) \
    asm volatile("ldmatrix.sync.aligned.m8n8.x4.shared.b16 {%0,%1,%2,%3}, [%4];" \
        : "=r"((r)[0]), "=r"((r)[1]), "=r"((r)[2]), "=r"((r)[3]) : "r"(a))

__device__ __forceinline__ void mma_bf16(float* c, const uint32_t* a,
                                         uint32_t b0, uint32_t b1) {
    asm volatile(
        "mma.sync.aligned.m16n8k16.row.col.f32.bf16.bf16.f32 "
        "{%0,%1,%2,%3}, {%4,%5,%6,%7}, {%8,%9}, {%0,%1,%2,%3};"
        : "+f"(c[0]), "+f"(c[1]), "+f"(c[2]), "+f"(c[3])
        : "r"(a[0]), "r"(a[1]), "r"(a[2]), "r"(a[3]), "r"(b0), "r"(b1));
}

__device__ __forceinline__ void split2(float x, float y, uint32_t& hi, uint32_t& lo) {
    __nv_bfloat16 hx = __float2bfloat16(x);
    __nv_bfloat16 hy = __float2bfloat16(y);
    __nv_bfloat16 lx = __float2bfloat16(x - __bfloat162float(hx));
    __nv_bfloat16 ly = __float2bfloat16(y - __bfloat162float(hy));
    hi = ((uint32_t)__bfloat16_as_ushort(hy) << 16) | __bfloat16_as_ushort(hx);
    lo = ((uint32_t)__bfloat16_as_ushort(ly) << 16) | __bfloat16_as_ushort(lx);
}

// ===========================================================================
// W pre-split: 6 fp32 128x128 matrices -> bf16 hi/lo planes
// ===========================================================================
__global__ void wsplit_kernel(const float* __restrict__ W0, const float* __restrict__ W1,
                              const float* __restrict__ W2, const float* __restrict__ W3,
                              const float* __restrict__ W4, const float* __restrict__ W5) {
    int t = blockIdx.x * blockDim.x + threadIdx.x;   // t < 6*4096
    if (t >= 6 * 4096) return;
    int m = t >> 12;
    int off = (t & 4095) << 2;   // element offset, multiple of 4
    const float* src = (m == 0) ? W0 : (m == 1) ? W1 : (m == 2) ? W2
                      : (m == 3) ? W3 : (m == 4) ? W4 : W5;
    float4 v = *reinterpret_cast<const float4*>(src + off);
    uint2 hv, lv;
    split2(v.x, v.y, hv.x, lv.x);
    split2(v.z, v.w, hv.y, lv.y);
    size_t p = (size_t)m * 16384 + off;
    *reinterpret_cast<uint2*>(g_wH + p) = hv;
    *reinterpret_cast<uint2*>(g_wL + p) = lv;
}

// ===========================================================================
// CSR build
// ===========================================================================
__global__ void zero_deg_kernel() {
    int t = blockIdx.x * blockDim.x + threadIdx.x;
    if (t < NN) g_deg[t] = 0;
}
__global__ void count_deg_kernel(const int* __restrict__ ei) {
    int e = blockIdx.x * blockDim.x + threadIdx.x;
    if (e < EE) atomicAdd(&g_deg[ei[EE + e]], 1);
}
// Exclusive scan; also zeroes g_deg for reuse as fill cursor.
__global__ void scan_kernel() {
    const int CH = (NN + 1023) / 1024;
    int t = threadIdx.x;
    int beg = t * CH;
    int end = min(beg + CH, NN);
    int sum = 0;
    for (int i = beg; i < end; i++) sum += g_deg[i];
    __shared__ int s[1024];
    s[t] = sum;
    __syncthreads();
    for (int off = 1; off < 1024; off <<= 1) {
        int v = (t >= off) ? s[t - off] : 0;
        __syncthreads();
        s[t] += v;
        __syncthreads();
    }
    int run = s[t] - sum;
    for (int i = beg; i < end; i++) {
        int d = g_deg[i];
        g_rowptr[i] = run;
        run += d;
        g_deg[i] = 0;     // reset cursor for fill (saves a launch)
    }
    if (t == 1023) g_rowptr[NN] = s[1023];
}
__global__ void fill_csr_kernel(const int* __restrict__ ei) {
    int e = blockIdx.x * blockDim.x + threadIdx.x;
    if (e >= EE) return;
    int d = ei[EE + e];
    int slot = atomicAdd(&g_deg[d], 1);
    g_csr[g_rowptr[d] + slot] = ei[e];
}

// ===========================================================================
// Gather-aggregate (CSR): warp per dst node, lane owns one float4; unroll 4
// ===========================================================================
__global__ void gather_kernel(const float* __restrict__ in,
                              float* __restrict__ agg) {
    int w = (blockIdx.x * blockDim.x + threadIdx.x) >> 5;
    int lane = threadIdx.x & 31;
    if (w >= NN) return;
    int beg = g_rowptr[w];
    int end = g_rowptr[w + 1];
    float4 a0 = make_float4(0.f, 0.f, 0.f, 0.f);
    float4 a1 = make_float4(0.f, 0.f, 0.f, 0.f);
    float4 a2 = make_float4(0.f, 0.f, 0.f, 0.f);
    float4 a3 = make_float4(0.f, 0.f, 0.f, 0.f);
    int i = beg;
    for (; i + 3 < end; i += 4) {
        int s0 = g_csr[i], s1 = g_csr[i + 1], s2 = g_csr[i + 2], s3 = g_csr[i + 3];
        float4 v0 = reinterpret_cast<const float4*>(in + (size_t)s0 * DD)[lane];
        float4 v1 = reinterpret_cast<const float4*>(in + (size_t)s1 * DD)[lane];
        float4 v2 = reinterpret_cast<const float4*>(in + (size_t)s2 * DD)[lane];
        float4 v3 = reinterpret_cast<const float4*>(in + (size_t)s3 * DD)[lane];
        a0.x += v0.x; a0.y += v0.y; a0.z += v0.z; a0.w += v0.w;
        a1.x += v1.x; a1.y += v1.y; a1.z += v1.z; a1.w += v1.w;
        a2.x += v2.x; a2.y += v2.y; a2.z += v2.z; a2.w += v2.w;
        a3.x += v3.x; a3.y += v3.y; a3.z += v3.z; a3.w += v3.w;
    }
    for (; i < end; i++) {
        int s0 = g_csr[i];
        float4 v0 = reinterpret_cast<const float4*>(in + (size_t)s0 * DD)[lane];
        a0.x += v0.x; a0.y += v0.y; a0.z += v0.z; a0.w += v0.w;
    }
    a0.x += a1.x + a2.x + a3.x;
    a0.y += a1.y + a2.y + a3.y;
    a0.z += a1.z + a2.z + a3.z;
    a0.w += a1.w + a2.w + a3.w;
    reinterpret_cast<float4*>(agg + (size_t)w * DD)[lane] = a0;
}

// ===========================================================================
// Split-bf16 mma.sync SAGE GEMM v3
//   64-row tile, N=128, occupancy 2, ldmatrix fragments, cp.async W copy.
//   out = maybe_relu(agg @ Wl^T + b + X @ Wr^T)
//   D += Ah@Wh + Ah@Wl + Al@Wh  (rel err ~1e-5)
// ===========================================================================
#define SP_B 272                      // smem row stride (68 words == 4 mod 32: conflict-free)
#define A_TILE_B (64 * SP_B)          // 17408
#define W_TILE_B (128 * SP_B)         // 34816
#define SM_BIAS  0
#define SM_AH    1024
#define SM_AL    (SM_AH + A_TILE_B)
#define SM_WH    (SM_AL + A_TILE_B)
#define SM_WL    (SM_WH + W_TILE_B)
#define SM_TOTAL (SM_WL + W_TILE_B)   // 105472 bytes -> 2 blocks/SM

__global__ __launch_bounds__(256, 2)
void sage_gemm_mma3_kernel(const float* __restrict__ A,
                           const float* __restrict__ X,
                           const uint16_t* __restrict__ WlH,
                           const uint16_t* __restrict__ WlL,
                           const uint16_t* __restrict__ WrH,
                           const uint16_t* __restrict__ WrL,
                           const float* __restrict__ bias,
                           float* __restrict__ out,
                           int relu) {
    extern __shared__ char smem[];
    uint32_t sb = smem_u32(smem);
    float* bs = (float*)(smem + SM_BIAS);

    int tid = threadIdx.x;
    int wid = tid >> 5;
    int lane = tid & 31;
    int wr = wid & 1;    // row group (32 rows)
    int wc = wid >> 1;   // col group (32 cols)
    int row0 = blockIdx.x * 64;
    if (tid < 128) bs[tid] = bias[tid];

    // ldmatrix lane addressing
    int i8 = lane & 7, q = lane >> 3;
    // A: matrices {(r0-7,k0),(r8-15,k0),(r0-7,k16B),(r8-15,k16B)} -> a0..a3
    uint32_t aAH = sb + SM_AH + (uint32_t)((wr * 32 + (q & 1) * 8 + i8) * SP_B + (q >> 1) * 16);
    uint32_t aAL = aAH + A_TILE_B;
    // B: matrices {(nfA,k0),(nfA,k16B),(nfB,k0),(nfB,k16B)} -> b0A,b1A,b0B,b1B
    uint32_t aWH = sb + SM_WH + (uint32_t)((wc * 32 + (q >> 1) * 8 + i8) * SP_B + (q & 1) * 16);
    uint32_t aWL = aWH + W_TILE_B;

    float acc[2][4][4];
#pragma unroll
    for (int mf = 0; mf < 2; mf++)
#pragma unroll
        for (int nf = 0; nf < 4; nf++)
#pragma unroll
            for (int c = 0; c < 4; c++) acc[mf][nf][c] = 0.f;

    for (int phase = 0; phase < 2; phase++) {
        const float* In = phase ? X : A;
        const uint16_t* WH = phase ? WrH : WlH;
        const uint16_t* WL = phase ? WrL : WlL;
        if (phase) __syncthreads();   // previous compute done before overwrite

        // W tiles via cp.async (pre-split, no conversion): 128 rows x 16 chunks x 2
        {
            const char* sH = (const char*)WH;
            const char* sL = (const char*)WL;
#pragma unroll
            for (int it = 0; it < 8; it++) {
                int idx = tid + it * 256;
                int r = idx >> 4, c = idx & 15;
                CP_ASYNC16(sb + SM_WH + r * SP_B + c * 16, sH + r * 256 + c * 16);
                CP_ASYNC16(sb + SM_WL + r * SP_B + c * 16, sL + r * 256 + c * 16);
            }
            CP_COMMIT();
        }
        // A tile: batched LDG (8 in flight) then convert+STS
        {
            float4 v[8];
#pragma unroll
            for (int it = 0; it < 8; it++) {
                int idx = tid + it * 256;
                int r = idx >> 5;
                int k4 = (idx & 31) << 2;
                v[it] = (row0 + r < NN)
                        ? *reinterpret_cast<const float4*>(In + (size_t)(row0 + r) * DD + k4)
                        : make_float4(0.f, 0.f, 0.f, 0.f);
            }
#pragma unroll
            for (int it = 0; it < 8; it++) {
                int idx = tid + it * 256;
                int r = idx >> 5;
                int k4 = (idx & 31) << 2;
                uint2 hv, lv;
                split2(v[it].x, v[it].y, hv.x, lv.x);
                split2(v[it].z, v[it].w, hv.y, lv.y);
                uint32_t off = (uint32_t)(r * SP_B + k4 * 2);
                *reinterpret_cast<uint2*>(smem + SM_AH + off) = hv;
                *reinterpret_cast<uint2*>(smem + SM_AL + off) = lv;
            }
        }
        CP_WAIT0();
        __syncthreads();

#pragma unroll
        for (int ks = 0; ks < 8; ks++) {
            uint32_t kb = ks * 32;
            uint32_t ah0[4], ah1[4], al0[4], al1[4];
            LDM4(ah0, aAH + kb);
            LDM4(ah1, aAH + 16 * SP_B + kb);
            LDM4(al0, aAL + kb);
            LDM4(al1, aAL + 16 * SP_B + kb);
            uint32_t bh0[4], bh1[4], bl0[4], bl1[4];
            LDM4(bh0, aWH + kb);                 // nf0, nf1
            LDM4(bh1, aWH + 16 * SP_B + kb);     // nf2, nf3
            LDM4(bl0, aWL + kb);
            LDM4(bl1, aWL + 16 * SP_B + kb);
#pragma unroll
            for (int mf = 0; mf < 2; mf++) {
                const uint32_t* ah = mf ? ah1 : ah0;
                const uint32_t* al = mf ? al1 : al0;
                mma_bf16(acc[mf][0], ah, bh0[0], bh0[1]);
                mma_bf16(acc[mf][1], ah, bh0[2], bh0[3]);
                mma_bf16(acc[mf][2], ah, bh1[0], bh1[1]);
                mma_bf16(acc[mf][3], ah, bh1[2], bh1[3]);
                mma_bf16(acc[mf][0], al, bh0[0], bh0[1]);
                mma_bf16(acc[mf][1], al, bh0[2], bh0[3]);
                mma_bf16(acc[mf][2], al, bh1[0], bh1[1]);
                mma_bf16(acc[mf][3], al, bh1[2], bh1[3]);
                mma_bf16(acc[mf][0], ah, bl0[0], bl0[1]);
                mma_bf16(acc[mf][1], ah, bl0[2], bl0[3]);
                mma_bf16(acc[mf][2], ah, bl1[0], bl1[1]);
                mma_bf16(acc[mf][3], ah, bl1[2], bl1[3]);
            }
        }
    }

    // Epilogue: rows (gr, gr+8) per 16-row mfrag; cols 2*(lane&3)+{0,1} per nfrag
    int gr = lane >> 2;
    int tk2 = (lane & 3) << 1;
#pragma unroll
    for (int mf = 0; mf < 2; mf++) {
#pragma unroll
        for (int half = 0; half < 2; half++) {
            int row = row0 + wr * 32 + mf * 16 + gr + half * 8;
            if (row >= NN) continue;
#pragma unroll
            for (int nf = 0; nf < 4; nf++) {
                int col = wc * 32 + nf * 8 + tk2;
                float v0 = acc[mf][nf][half * 2 + 0] + bs[col];
                float v1 = acc[mf][nf][half * 2 + 1] + bs[col + 1];
                if (relu) { v0 = fmaxf(v0, 0.f); v1 = fmaxf(v1, 0.f); }
                *reinterpret_cast<float2*>(out + (size_t)row * DD + col) =
                    make_float2(v0, v1);
            }
        }
    }
}

// ===========================================================================
// Pool + final linear
// ===========================================================================
__global__ void zero_pool_kernel() {
    int t = blockIdx.x * blockDim.x + threadIdx.x;
    if (t < NG * DD) g_pool[t] = 0.f;
    if (t < NG) g_cnt[t] = 0.f;
}
__global__ void pool_kernel(const float* __restrict__ h,
                            const int* __restrict__ batch) {
    int t = blockIdx.x * blockDim.x + threadIdx.x;
    int n = t >> 5;
    int lane = t & 31;
    if (n >= NN) return;
    int g = batch[n];
    float4 v = reinterpret_cast<const float4*>(h + (size_t)n * DD)[lane];
    float* dp = g_pool + (size_t)g * DD + lane * 4;
    asm volatile("red.global.add.v4.f32 [%0], {%1,%2,%3,%4};"
                 :: "l"(dp), "f"(v.x), "f"(v.y), "f"(v.z), "f"(v.w) : "memory");
    if (lane == 0) atomicAdd(&g_cnt[g], 1.0f);
}
__global__ void final_kernel(const float* __restrict__ Wlin,
                             const float* __restrict__ blin,
                             float* __restrict__ out) {
    int g = blockIdx.x;
    int o = threadIdx.x;
    __shared__ float ps[DD];
    ps[o] = g_pool[g * DD + o];
    ps[o + 64] = g_pool[g * DD + o + 64];
    __syncthreads();
    float inv = 1.f / fmaxf(g_cnt[g], 1.f);
    float dot = 0.f;
#pragma unroll 4
    for (int k = 0; k < DD; k++) dot += ps[k] * Wlin[o * DD + k];
    out[g * OUTD + o] = dot * inv + blin[o];
}

// ===========================================================================
extern "C" void kernel_launch(void* const* d_in, const int* in_sizes, int n_in,
                              void* d_out, int out_size) {
    const float* x    = (const float*)d_in[0];
    const int*   ei   = (const int*)d_in[1];
    const int*   batch= (const int*)d_in[2];
    const float* W1l  = (const float*)d_in[3];
    const float* b1l  = (const float*)d_in[4];
    const float* W1r  = (const float*)d_in[5];
    const float* W2l  = (const float*)d_in[6];
    const float* b2l  = (const float*)d_in[7];
    const float* W2r  = (const float*)d_in[8];
    const float* W3l  = (const float*)d_in[9];
    const float* b3l  = (const float*)d_in[10];
    const float* W3r  = (const float*)d_in[11];
    const float* Wlin = (const float*)d_in[12];
    const float* blin = (const float*)d_in[13];
    float* out = (float*)d_out;

    cudaFuncSetAttribute(sage_gemm_mma3_kernel,
                         cudaFuncAttributeMaxDynamicSharedMemorySize, SM_TOTAL);

    const int nodeBlocks = (NN + 255) / 256;
    const int edgeBlocks = (EE + 255) / 256;
    const int gatherBlocks = (NN * 32 + 255) / 256;
    const int gemmBlocks = (NN + 63) / 64;
    const int poolBlocks = (NN * 32 + 255) / 256;

    float* devAgg;  cudaGetSymbolAddress((void**)&devAgg, g_agg);
    float* devA;    cudaGetSymbolAddress((void**)&devA, g_bufA);
    float* devB;    cudaGetSymbolAddress((void**)&devB, g_bufB);
    uint16_t* wH;   cudaGetSymbolAddress((void**)&wH, g_wH);
    uint16_t* wL;   cudaGetSymbolAddress((void**)&wL, g_wL);

    // Pre-split all 6 weight matrices into bf16 hi/lo planes
    wsplit_kernel<<<96, 256>>>(W1l, W1r, W2l, W2r, W3l, W3r);

    // Build CSR (dst-grouped) once; reused by all 3 layers.
    zero_deg_kernel<<<nodeBlocks, 256>>>();
    count_deg_kernel<<<edgeBlocks, 256>>>(ei);
    scan_kernel<<<1, 1024>>>();     // also resets g_deg cursors
    fill_csr_kernel<<<edgeBlocks, 256>>>(ei);

    // Layer 1
    gather_kernel<<<gatherBlocks, 256>>>(x, devAgg);
    sage_gemm_mma3_kernel<<<gemmBlocks, 256, SM_TOTAL>>>(
        devAgg, x, wH + 0 * 16384, wL + 0 * 16384, wH + 1 * 16384, wL + 1 * 16384,
        b1l, devA, 1);
    // Layer 2
    gather_kernel<<<gatherBlocks, 256>>>(devA, devAgg);
    sage_gemm_mma3_kernel<<<gemmBlocks, 256, SM_TOTAL>>>(
        devAgg, devA, wH + 2 * 16384, wL + 2 * 16384, wH + 3 * 16384, wL + 3 * 16384,
        b2l, devB, 1);
    // Layer 3
    gather_kernel<<<gatherBlocks, 256>>>(devB, devAgg);
    sage_gemm_mma3_kernel<<<gemmBlocks, 256, SM_TOTAL>>>(
        devAgg, devB, wH + 4 * 16384, wL + 4 * 16384, wH + 5 * 16384, wL + 5 * 16384,
        b3l, devA, 0);
    // Pool + final linear
    zero_pool_kernel<<<(NG * DD + 255) / 256, 256>>>();
    pool_kernel<<<poolBlocks, 256>>>(devA, batch);
    final_kernel<<<NG, OUTD>>>(Wlin, blin, out);
}

// round 15
// speedup vs baseline: 1.0786x; 1.0786x over previous
#include <cuda_runtime.h>
#include <cuda_bf16.h>
#include <cstdint>

#define NN 50000
#define EE 800000
#define DD 128
#define OUTD 64
#define NG 64
#define NB 196            // scan blocks (196*256 >= NN)

// Scratch (device globals; no allocation allowed)
__device__ float g_agg[NN * DD];
__device__ float g_bufA[NN * DD];
__device__ float g_bufB[NN * DD];
__device__ float g_pool[NG * DD];
__device__ float g_cnt[NG];
__device__ int   g_deg[NN];
__device__ int   g_rowptr[NN + 1];
__device__ int   g_csr[EE];
__device__ int   g_blksum[NB];
__device__ int   g_blkoff[NB];

// ===========================================================================
// CSR build (hierarchical scan)
// ===========================================================================
__global__ void zero_deg_kernel() {
    int t = blockIdx.x * blockDim.x + threadIdx.x;
    if (t < NN) g_deg[t] = 0;
}
__global__ void count_deg_kernel(const int* __restrict__ ei) {
    int e = blockIdx.x * blockDim.x + threadIdx.x;
    if (e < EE) atomicAdd(&g_deg[ei[EE + e]], 1);
}
// Stage 1: per-block sums of 256 degrees
__global__ void scan_blksum_kernel() {
    int t = blockIdx.x * blockDim.x + threadIdx.x;
    int v = (t < NN) ? g_deg[t] : 0;
#pragma unroll
    for (int off = 16; off > 0; off >>= 1)
        v += __shfl_down_sync(0xFFFFFFFF, v, off);
    __shared__ int ws[8];
    if ((threadIdx.x & 31) == 0) ws[threadIdx.x >> 5] = v;
    __syncthreads();
    if (threadIdx.x == 0) {
        int s = 0;
#pragma unroll
        for (int i = 0; i < 8; i++) s += ws[i];
        g_blksum[blockIdx.x] = s;
    }
}
// Stage 2: one block scans NB block sums -> exclusive offsets + total
__global__ void scan_offsets_kernel() {
    int t = threadIdx.x;   // 256 >= NB
    int v = (t < NB) ? g_blksum[t] : 0;
    __shared__ int s[256];
    s[t] = v;
    __syncthreads();
    for (int off = 1; off < 256; off <<= 1) {
        int u = (t >= off) ? s[t - off] : 0;
        __syncthreads();
        s[t] += u;
        __syncthreads();
    }
    if (t < NB) g_blkoff[t] = s[t] - v;   // exclusive
    if (t == 255) g_rowptr[NN] = s[255];
}
// Stage 3: rescan within block, add offset, write rowptr, reset cursor
__global__ void scan_final_kernel() {
    int t = blockIdx.x * blockDim.x + threadIdx.x;
    int v = (t < NN) ? g_deg[t] : 0;
    __shared__ int s[256];
    s[threadIdx.x] = v;
    __syncthreads();
    for (int off = 1; off < 256; off <<= 1) {
        int u = (threadIdx.x >= off) ? s[threadIdx.x - off] : 0;
        __syncthreads();
        s[threadIdx.x] += u;
        __syncthreads();
    }
    if (t < NN) {
        g_rowptr[t] = g_blkoff[blockIdx.x] + s[threadIdx.x] - v;
        g_deg[t] = 0;   // reset cursor for fill
    }
}
__global__ void fill_csr_kernel(const int* __restrict__ ei) {
    int e = blockIdx.x * blockDim.x + threadIdx.x;
    if (e >= EE) return;
    int d = ei[EE + e];
    int slot = atomicAdd(&g_deg[d], 1);
    g_csr[g_rowptr[d] + slot] = ei[e];
}

// ===========================================================================
// Gather-aggregate (CSR): warp per dst node, lane owns one float4; unroll 4
// ===========================================================================
__global__ void gather_kernel(const float* __restrict__ in,
                              float* __restrict__ agg) {
    int w = (blockIdx.x * blockDim.x + threadIdx.x) >> 5;
    int lane = threadIdx.x & 31;
    if (w >= NN) return;
    int beg = g_rowptr[w];
    int end = g_rowptr[w + 1];
    float4 a0 = make_float4(0.f, 0.f, 0.f, 0.f);
    float4 a1 = make_float4(0.f, 0.f, 0.f, 0.f);
    float4 a2 = make_float4(0.f, 0.f, 0.f, 0.f);
    float4 a3 = make_float4(0.f, 0.f, 0.f, 0.f);
    int i = beg;
    for (; i + 3 < end; i += 4) {
        int s0 = g_csr[i], s1 = g_csr[i + 1], s2 = g_csr[i + 2], s3 = g_csr[i + 3];
        float4 v0 = reinterpret_cast<const float4*>(in + (size_t)s0 * DD)[lane];
        float4 v1 = reinterpret_cast<const float4*>(in + (size_t)s1 * DD)[lane];
        float4 v2 = reinterpret_cast<const float4*>(in + (size_t)s2 * DD)[lane];
        float4 v3 = reinterpret_cast<const float4*>(in + (size_t)s3 * DD)[lane];
        a0.x += v0.x; a0.y += v0.y; a0.z += v0.z; a0.w += v0.w;
        a1.x += v1.x; a1.y += v1.y; a1.z += v1.z; a1.w += v1.w;
        a2.x += v2.x; a2.y += v2.y; a2.z += v2.z; a2.w += v2.w;
        a3.x += v3.x; a3.y += v3.y; a3.z += v3.z; a3.w += v3.w;
    }
    for (; i < end; i++) {
        int s0 = g_csr[i];
        float4 v0 = reinterpret_cast<const float4*>(in + (size_t)s0 * DD)[lane];
        a0.x += v0.x; a0.y += v0.y; a0.z += v0.z; a0.w += v0.w;
    }
    a0.x += a1.x + a2.x + a3.x;
    a0.y += a1.y + a2.y + a3.y;
    a0.z += a1.z + a2.z + a3.z;
    a0.w += a1.w + a2.w + a3.w;
    reinterpret_cast<float4*>(agg + (size_t)w * DD)[lane] = a0;
}

// ===========================================================================
// Split-bf16 mma.sync SAGE GEMM (R9-measured v2 config)
//   out[128-row tile] = maybe_relu(agg @ Wl^T + b + X @ Wr^T)
// fp32 = hi(bf16) + lo(bf16); D += Ah@Wh + Ah@Wl + Al@Wh (rel err ~1e-5).
// m16n8k16 fragments read k-pairs directly from row-major bf16 smem tiles
// with 272-byte row stride (conflict-free: bank = 4*row + (lane&3)).
// ===========================================================================
#define SP_B 272                     // smem row stride bytes (136 bf16)
#define TILE_B (128 * SP_B)          // 34816 bytes per tile buffer
#define SM_BIAS 0                    // 512 bytes
#define SM_AH   1024
#define SM_AL   (SM_AH + TILE_B)
#define SM_WH   (SM_AL + TILE_B)
#define SM_WL   (SM_WH + TILE_B)
#define SM_TOTAL (SM_WL + TILE_B)

__device__ __forceinline__ void mma_bf16(float* c, const uint32_t* a,
                                         uint32_t b0, uint32_t b1) {
    asm volatile(
        "mma.sync.aligned.m16n8k16.row.col.f32.bf16.bf16.f32 "
        "{%0,%1,%2,%3}, {%4,%5,%6,%7}, {%8,%9}, {%0,%1,%2,%3};"
        : "+f"(c[0]), "+f"(c[1]), "+f"(c[2]), "+f"(c[3])
        : "r"(a[0]), "r"(a[1]), "r"(a[2]), "r"(a[3]), "r"(b0), "r"(b1));
}

// Convert a 128x128 fp32 tile into hi/lo bf16 smem tiles (row-major, SP_B).
__device__ __forceinline__ void convert_tile(const float* __restrict__ src,
                                             int row0, int nrows,
                                             char* dstH, char* dstL, int tid) {
    for (int idx = tid; idx < 128 * 32; idx += 256) {
        int r = idx >> 5;
        int k4 = (idx & 31) << 2;
        float4 v;
        if (row0 + r < nrows)
            v = *reinterpret_cast<const float4*>(src + (size_t)(row0 + r) * DD + k4);
        else
            v = make_float4(0.f, 0.f, 0.f, 0.f);
        __nv_bfloat16 h0 = __float2bfloat16(v.x);
        __nv_bfloat16 h1 = __float2bfloat16(v.y);
        __nv_bfloat16 h2 = __float2bfloat16(v.z);
        __nv_bfloat16 h3 = __float2bfloat16(v.w);
        __nv_bfloat16 l0 = __float2bfloat16(v.x - __bfloat162float(h0));
        __nv_bfloat16 l1 = __float2bfloat16(v.y - __bfloat162float(h1));
        __nv_bfloat16 l2 = __float2bfloat16(v.z - __bfloat162float(h2));
        __nv_bfloat16 l3 = __float2bfloat16(v.w - __bfloat162float(h3));
        uint2 hv, lv;
        hv.x = ((uint32_t)__bfloat16_as_ushort(h1) << 16) | __bfloat16_as_ushort(h0);
        hv.y = ((uint32_t)__bfloat16_as_ushort(h3) << 16) | __bfloat16_as_ushort(h2);
        lv.x = ((uint32_t)__bfloat16_as_ushort(l1) << 16) | __bfloat16_as_ushort(l0);
        lv.y = ((uint32_t)__bfloat16_as_ushort(l3) << 16) | __bfloat16_as_ushort(l2);
        uint32_t off = (uint32_t)(r * SP_B + k4 * 2);
        *reinterpret_cast<uint2*>(dstH + off) = hv;
        *reinterpret_cast<uint2*>(dstL + off) = lv;
    }
}

__global__ __launch_bounds__(256, 1)
void sage_gemm_mma_kernel(const float* __restrict__ A,
                          const float* __restrict__ X,
                          const float* __restrict__ Wl,
                          const float* __restrict__ Wr,
                          const float* __restrict__ bias,
                          float* __restrict__ out,
                          int relu) {
    extern __shared__ char smem[];
    char* sAH = smem + SM_AH;
    char* sAL = smem + SM_AL;
    char* sWH = smem + SM_WH;
    char* sWL = smem + SM_WL;
    float* bs = (float*)(smem + SM_BIAS);

    int tid = threadIdx.x;
    int wid = tid >> 5;
    int lane = tid & 31;
    int wr = wid & 3;    // row group: rows wr*32 .. +32
    int wc = wid >> 2;   // col group: cols wc*64 .. +64
    int gr = lane >> 2;          // 0..7
    int ko = (lane & 3) << 2;    // k byte offset within 32B k-step

    int row0 = blockIdx.x * 128;
    if (tid < 128) bs[tid] = bias[tid];

    float acc[2][8][4];
#pragma unroll
    for (int mf = 0; mf < 2; mf++)
#pragma unroll
        for (int nf = 0; nf < 8; nf++)
#pragma unroll
            for (int q = 0; q < 4; q++) acc[mf][nf][q] = 0.f;

    for (int phase = 0; phase < 2; phase++) {
        const float* In = phase ? X : A;
        const float* W = phase ? Wr : Wl;
        if (phase) __syncthreads();  // previous phase's MMAs done before overwrite
        convert_tile(In, row0, NN, sAH, sAL, tid);
        convert_tile(W, 0, 128, sWH, sWL, tid);
        __syncthreads();

        const char* pa0 = sAH + (wr * 32 + gr) * SP_B + ko;
        const char* pl0 = sAL + (wr * 32 + gr) * SP_B + ko;
        const char* pbh = sWH + (wc * 64 + gr) * SP_B + ko;
        const char* pbl = sWL + (wc * 64 + gr) * SP_B + ko;

#pragma unroll
        for (int ks = 0; ks < 8; ks++) {
            int kb = ks * 32;
            uint32_t ah[2][4], al[2][4];
#pragma unroll
            for (int mf = 0; mf < 2; mf++) {
                const char* pa = pa0 + mf * 16 * SP_B + kb;
                ah[mf][0] = *(const uint32_t*)(pa);
                ah[mf][1] = *(const uint32_t*)(pa + 8 * SP_B);
                ah[mf][2] = *(const uint32_t*)(pa + 16);
                ah[mf][3] = *(const uint32_t*)(pa + 8 * SP_B + 16);
                const char* pl = pl0 + mf * 16 * SP_B + kb;
                al[mf][0] = *(const uint32_t*)(pl);
                al[mf][1] = *(const uint32_t*)(pl + 8 * SP_B);
                al[mf][2] = *(const uint32_t*)(pl + 16);
                al[mf][3] = *(const uint32_t*)(pl + 8 * SP_B + 16);
            }
#pragma unroll
            for (int nf = 0; nf < 8; nf++) {
                const char* ph = pbh + nf * 8 * SP_B + kb;
                uint32_t bh0 = *(const uint32_t*)(ph);
                uint32_t bh1 = *(const uint32_t*)(ph + 16);
                const char* pw = pbl + nf * 8 * SP_B + kb;
                uint32_t bl0 = *(const uint32_t*)(pw);
                uint32_t bl1 = *(const uint32_t*)(pw + 16);
                mma_bf16(acc[0][nf], ah[0], bh0, bh1);
                mma_bf16(acc[1][nf], ah[1], bh0, bh1);
                mma_bf16(acc[0][nf], al[0], bh0, bh1);
                mma_bf16(acc[1][nf], al[1], bh0, bh1);
                mma_bf16(acc[0][nf], ah[0], bl0, bl1);
                mma_bf16(acc[1][nf], ah[1], bl0, bl1);
            }
        }
    }

    // Epilogue: C thread map: rows (gr, gr+8) of each 16-row mfrag,
    // cols 2*(lane&3)+{0,1} of each 8-col nfrag.
    int crow0 = row0 + wr * 32;
    int ccol0 = wc * 64 + ((lane & 3) << 1);
#pragma unroll
    for (int mf = 0; mf < 2; mf++) {
#pragma unroll
        for (int half = 0; half < 2; half++) {
            int row = crow0 + mf * 16 + gr + half * 8;
            if (row >= NN) continue;
#pragma unroll
            for (int nf = 0; nf < 8; nf++) {
                int col = ccol0 + nf * 8;
                float v0 = acc[mf][nf][half * 2 + 0] + bs[col];
                float v1 = acc[mf][nf][half * 2 + 1] + bs[col + 1];
                if (relu) { v0 = fmaxf(v0, 0.f); v1 = fmaxf(v1, 0.f); }
                *reinterpret_cast<float2*>(out + (size_t)row * DD + col) =
                    make_float2(v0, v1);
            }
        }
    }
}

// ===========================================================================
// Pool + final linear
// ===========================================================================
__global__ void zero_pool_kernel() {
    int t = blockIdx.x * blockDim.x + threadIdx.x;
    if (t < NG * DD) g_pool[t] = 0.f;
    if (t < NG) g_cnt[t] = 0.f;
}
__global__ void pool_kernel(const float* __restrict__ h,
                            const int* __restrict__ batch) {
    int t = blockIdx.x * blockDim.x + threadIdx.x;
    int n = t >> 5;
    int lane = t & 31;
    if (n >= NN) return;
    int g = batch[n];
    float4 v = reinterpret_cast<const float4*>(h + (size_t)n * DD)[lane];
    float* dp = g_pool + (size_t)g * DD + lane * 4;
    asm volatile("red.global.add.v4.f32 [%0], {%1,%2,%3,%4};"
                 :: "l"(dp), "f"(v.x), "f"(v.y), "f"(v.z), "f"(v.w) : "memory");
    if (lane == 0) atomicAdd(&g_cnt[g], 1.0f);
}
__global__ void final_kernel(const float* __restrict__ Wlin,
                             const float* __restrict__ blin,
                             float* __restrict__ out) {
    int g = blockIdx.x;
    int o = threadIdx.x;
    __shared__ float ps[DD];
    ps[o] = g_pool[g * DD + o];
    ps[o + 64] = g_pool[g * DD + o + 64];
    __syncthreads();
    float inv = 1.f / fmaxf(g_cnt[g], 1.f);
    float dot = 0.f;
#pragma unroll 4
    for (int k = 0; k < DD; k++) dot += ps[k] * Wlin[o * DD + k];
    out[g * OUTD + o] = dot * inv + blin[o];
}

// ===========================================================================
extern "C" void kernel_launch(void* const* d_in, const int* in_sizes, int n_in,
                              void* d_out, int out_size) {
    const float* x    = (const float*)d_in[0];
    const int*   ei   = (const int*)d_in[1];
    const int*   batch= (const int*)d_in[2];
    const float* W1l  = (const float*)d_in[3];
    const float* b1l  = (const float*)d_in[4];
    const float* W1r  = (const float*)d_in[5];
    const float* W2l  = (const float*)d_in[6];
    const float* b2l  = (const float*)d_in[7];
    const float* W2r  = (const float*)d_in[8];
    const float* W3l  = (const float*)d_in[9];
    const float* b3l  = (const float*)d_in[10];
    const float* W3r  = (const float*)d_in[11];
    const float* Wlin = (const float*)d_in[12];
    const float* blin = (const float*)d_in[13];
    float* out = (float*)d_out;

    cudaFuncSetAttribute(sage_gemm_mma_kernel,
                         cudaFuncAttributeMaxDynamicSharedMemorySize, SM_TOTAL);

    const int nodeBlocks = NB;                     // 196*256 >= NN
    const int edgeBlocks = (EE + 255) / 256;
    const int gatherBlocks = (NN * 32 + 255) / 256;
    const int gemmBlocks = (NN + 127) / 128;
    const int poolBlocks = (NN * 32 + 255) / 256;

    float* devAgg;  cudaGetSymbolAddress((void**)&devAgg, g_agg);
    float* devA;    cudaGetSymbolAddress((void**)&devA, g_bufA);
    float* devB;    cudaGetSymbolAddress((void**)&devB, g_bufB);

    // Build CSR (dst-grouped) once; hierarchical scan (no serial bottleneck).
    zero_deg_kernel<<<nodeBlocks, 256>>>();
    count_deg_kernel<<<edgeBlocks, 256>>>(ei);
    scan_blksum_kernel<<<NB, 256>>>();
    scan_offsets_kernel<<<1, 256>>>();
    scan_final_kernel<<<NB, 256>>>();   // writes rowptr, resets g_deg cursors
    fill_csr_kernel<<<edgeBlocks, 256>>>(ei);

    // Layer 1
    gather_kernel<<<gatherBlocks, 256>>>(x, devAgg);
    sage_gemm_mma_kernel<<<gemmBlocks, 256, SM_TOTAL>>>(devAgg, x, W1l, W1r, b1l, devA, 1);
    // Layer 2
    gather_kernel<<<gatherBlocks, 256>>>(devA, devAgg);
    sage_gemm_mma_kernel<<<gemmBlocks, 256, SM_TOTAL>>>(devAgg, devA, W2l, W2r, b2l, devB, 1);
    // Layer 3
    gather_kernel<<<gatherBlocks, 256>>>(devB, devAgg);
    sage_gemm_mma_kernel<<<gemmBlocks, 256, SM_TOTAL>>>(devAgg, devB, W3l, W3r, b3l, devA, 0);
    // Pool + final linear
    zero_pool_kernel<<<(NG * DD + 255) / 256, 256>>>();
    pool_kernel<<<poolBlocks, 256>>>(devA, batch);
    final_kernel<<<NG, OUTD>>>(Wlin, blin, out);
}